// round 10
// baseline (speedup 1.0000x reference)
#include <cuda_runtime.h>
#include <cuda_bf16.h>
#include <cstdint>

// -(1/B) * sum(preds_t * log(preds_s)),  B = 4096, C = 1000  (n = 4,096,000)
// Contiguous per-CTA chunks + cp.async.bulk.prefetch.L2 (bulk engine issues the
// DRAM stream as sequential bursts, decoupled from register scheduling), then
// plain vectorized LDGs that hit/merge with the in-flight L2 fills.
// n_vec = 1,024,000 float4 = 2000 CTAs x 256 thr x 2 float4/thread exactly.

#define NTHR    256
#define VPT     2                      // float4 per thread per array
#define NBLK_EX 2000
#define CHUNK_V4 (NTHR * VPT)          // 512 float4 per array per CTA
#define CHUNK_B  (CHUNK_V4 * 16)       // 8192 bytes
#define MAXBLK  2048

__device__ float g_partials[MAXBLK];
__device__ unsigned int g_ticket;      // zero-init; reset by last block each call

__device__ __forceinline__ float block_reduce(float acc, float* warp_sums)
{
    #pragma unroll
    for (int off = 16; off > 0; off >>= 1)
        acc += __shfl_xor_sync(0xFFFFFFFFu, acc, off);

    int lane = threadIdx.x & 31;
    int wid  = threadIdx.x >> 5;
    if (lane == 0) warp_sums[wid] = acc;
    __syncthreads();

    float v = 0.0f;
    if (wid == 0) {
        v = (lane < NTHR / 32) ? warp_sums[lane] : 0.0f;
        #pragma unroll
        for (int off = 4; off > 0; off >>= 1)
            v += __shfl_xor_sync(0xFFFFFFFFu, v, off);
    }
    return v;   // valid in warp 0 lane 0
}

__device__ __forceinline__ void finish(float acc, float inv_B, float* out, int nblk)
{
    __shared__ float warp_sums[NTHR / 32];
    float bsum = block_reduce(acc, warp_sums);

    __shared__ bool is_last;
    if (threadIdx.x == 0) {
        g_partials[blockIdx.x] = bsum;
        __threadfence();
        unsigned int ticket = atomicAdd(&g_ticket, 1u);
        is_last = (ticket == (unsigned int)(nblk - 1));
    }
    __syncthreads();

    if (is_last) {
        float a = 0.0f;
        for (int i = threadIdx.x; i < nblk; i += NTHR)
            a += g_partials[i];
        __syncthreads();
        float total = block_reduce(a, warp_sums);
        if (threadIdx.x == 0) {
            out[0] = -total * inv_B;
            g_ticket = 0;                   // reset for next graph replay
        }
    }
}

__global__ __launch_bounds__(NTHR) void pf_reduce(
    const float4* __restrict__ s4, const float4* __restrict__ t4,
    float inv_B, float* __restrict__ out)
{
    const int  tid  = threadIdx.x;
    const long base = (long)blockIdx.x * CHUNK_V4;

    // Hand the whole chunk (both arrays) to the bulk engine: sequential 8KB
    // bursts into L2, no registers, no SM-side tracking.
    if (tid == 0) {
        asm volatile("cp.async.bulk.prefetch.L2.global [%0], %1;"
                     :: "l"(s4 + base), "n"(CHUNK_B) : "memory");
        asm volatile("cp.async.bulk.prefetch.L2.global [%0], %1;"
                     :: "l"(t4 + base), "n"(CHUNK_B) : "memory");
    }

    // Demand loads: contiguous within the chunk, 4 LDG.128 per thread.
    float4 sv0 = s4[base + tid];
    float4 tv0 = t4[base + tid];
    float4 sv1 = s4[base + tid + NTHR];
    float4 tv1 = t4[base + tid + NTHR];

    float acc = 0.0f;
    acc += tv0.x * __logf(sv0.x);
    acc += tv0.y * __logf(sv0.y);
    acc += tv0.z * __logf(sv0.z);
    acc += tv0.w * __logf(sv0.w);
    acc += tv1.x * __logf(sv1.x);
    acc += tv1.y * __logf(sv1.y);
    acc += tv1.z * __logf(sv1.z);
    acc += tv1.w * __logf(sv1.w);

    finish(acc, inv_B, out, NBLK_EX);
}

// Generic fallback (any n), grid-stride. Only used if shape isn't exact-cover.
__global__ __launch_bounds__(NTHR) void fused_reduce_generic(
    const float* __restrict__ s, const float* __restrict__ t,
    int n, float inv_B, float* __restrict__ out, int nblk)
{
    int n_vec = n / 4;
    int tail0 = n_vec * 4;
    const float4* s4 = reinterpret_cast<const float4*>(s);
    const float4* t4 = reinterpret_cast<const float4*>(t);

    float acc = 0.0f;
    int stride = nblk * NTHR;
    for (int i = blockIdx.x * NTHR + threadIdx.x; i < n_vec; i += stride) {
        float4 sv = s4[i];
        float4 tv = t4[i];
        acc += tv.x * __logf(sv.x);
        acc += tv.y * __logf(sv.y);
        acc += tv.z * __logf(sv.z);
        acc += tv.w * __logf(sv.w);
    }
    if (blockIdx.x == 0) {
        for (int i = tail0 + threadIdx.x; i < n; i += NTHR)
            acc += t[i] * __logf(s[i]);
    }

    finish(acc, inv_B, out, nblk);
}

extern "C" void kernel_launch(void* const* d_in, const int* in_sizes, int n_in,
                              void* d_out, int out_size)
{
    const float* s = (const float*)d_in[0];  // preds_s
    const float* t = (const float*)d_in[1];  // preds_t
    float* out = (float*)d_out;

    int n = in_sizes[0];
    float inv_B = (n == 4096000) ? (1.0f / 4096.0f) : (1000.0f / (float)n);

    int n_vec = n / 4;

    if ((n % 4 == 0) && (n_vec == NBLK_EX * CHUNK_V4)) {
        pf_reduce<<<NBLK_EX, NTHR>>>(
            reinterpret_cast<const float4*>(s),
            reinterpret_cast<const float4*>(t),
            inv_B, out);
    } else {
        int nblk = 1024;
        fused_reduce_generic<<<nblk, NTHR>>>(s, t, n, inv_B, out, nblk);
    }
}

// round 11
// speedup vs baseline: 1.4317x; 1.4317x over previous
#include <cuda_runtime.h>
#include <cuda_bf16.h>
#include <cstdint>

// -(1/B) * sum(preds_t * log(preds_s)),  B = 4096, C = 1000  (n = 4,096,000)
// Best-known structure (R5) with overhead trims:
//   n_vec = 1,024,000 float4 = 500 blocks x 512 threads x 4 vec/thread exactly.
//   Tail: release-atomic ticket (no separate MEMBAR), last-block fold.

#define NTHR    512
#define VPT     4
#define NBLK_EX 500
#define MAXBLK  2048

__device__ float g_partials[MAXBLK];
__device__ unsigned int g_ticket;   // zero-init; reset by last block each call

__device__ __forceinline__ float block_reduce(float acc, float* warp_sums)
{
    #pragma unroll
    for (int off = 16; off > 0; off >>= 1)
        acc += __shfl_xor_sync(0xFFFFFFFFu, acc, off);

    int lane = threadIdx.x & 31;
    int wid  = threadIdx.x >> 5;
    if (lane == 0) warp_sums[wid] = acc;
    __syncthreads();

    float v = 0.0f;
    if (wid == 0) {
        v = (lane < NTHR / 32) ? warp_sums[lane] : 0.0f;
        #pragma unroll
        for (int off = 8; off > 0; off >>= 1)
            v += __shfl_xor_sync(0xFFFFFFFFu, v, off);
    }
    return v;   // valid in warp 0 lane 0
}

__device__ __forceinline__ void finish(float acc, float inv_B, float* out, int nblk)
{
    __shared__ float warp_sums[NTHR / 32];
    float bsum = block_reduce(acc, warp_sums);

    __shared__ bool is_last;
    if (threadIdx.x == 0) {
        g_partials[blockIdx.x] = bsum;
        // release-atomic ticket: orders the partial store before the ticket
        // without a separate __threadfence()
        unsigned int ticket;
        asm volatile("atom.release.gpu.global.add.u32 %0, [%1], 1;"
                     : "=r"(ticket) : "l"(&g_ticket) : "memory");
        is_last = (ticket == (unsigned int)(nblk - 1));
    }
    __syncthreads();

    if (is_last) {
        float a = 0.0f;
        for (int i = threadIdx.x; i < nblk; i += NTHR)
            a += g_partials[i];
        __syncthreads();
        float total = block_reduce(a, warp_sums);
        if (threadIdx.x == 0) {
            out[0] = -total * inv_B;
            g_ticket = 0;                   // reset for next graph replay
        }
    }
}

__global__ __launch_bounds__(NTHR) void fused_reduce_exact(
    const float4* __restrict__ s4, const float4* __restrict__ t4,
    float inv_B, float* __restrict__ out)
{
    const int idx = blockIdx.x * NTHR + threadIdx.x;
    const int stride = NBLK_EX * NTHR;          // 256,000 float4

    float a0 = 0.0f, a1 = 0.0f;
    #pragma unroll
    for (int u = 0; u < VPT; u += 2) {
        float4 sv0 = s4[idx + (u + 0) * stride];
        float4 tv0 = t4[idx + (u + 0) * stride];
        float4 sv1 = s4[idx + (u + 1) * stride];
        float4 tv1 = t4[idx + (u + 1) * stride];

        a0 += tv0.x * __logf(sv0.x);
        a1 += tv0.y * __logf(sv0.y);
        a0 += tv0.z * __logf(sv0.z);
        a1 += tv0.w * __logf(sv0.w);
        a0 += tv1.x * __logf(sv1.x);
        a1 += tv1.y * __logf(sv1.y);
        a0 += tv1.z * __logf(sv1.z);
        a1 += tv1.w * __logf(sv1.w);
    }

    finish(a0 + a1, inv_B, out, NBLK_EX);
}

// Generic fallback (any n), grid-stride. Only used if shape isn't exact-cover.
__global__ __launch_bounds__(NTHR) void fused_reduce_generic(
    const float* __restrict__ s, const float* __restrict__ t,
    int n, float inv_B, float* __restrict__ out, int nblk)
{
    int n_vec = n / 4;
    int tail0 = n_vec * 4;
    const float4* s4 = reinterpret_cast<const float4*>(s);
    const float4* t4 = reinterpret_cast<const float4*>(t);

    float acc = 0.0f;
    int stride = nblk * NTHR;
    for (int i = blockIdx.x * NTHR + threadIdx.x; i < n_vec; i += stride) {
        float4 sv = s4[i];
        float4 tv = t4[i];
        acc += tv.x * __logf(sv.x);
        acc += tv.y * __logf(sv.y);
        acc += tv.z * __logf(sv.z);
        acc += tv.w * __logf(sv.w);
    }
    if (blockIdx.x == 0) {
        for (int i = tail0 + threadIdx.x; i < n; i += NTHR)
            acc += t[i] * __logf(s[i]);
    }

    finish(acc, inv_B, out, nblk);
}

extern "C" void kernel_launch(void* const* d_in, const int* in_sizes, int n_in,
                              void* d_out, int out_size)
{
    const float* s = (const float*)d_in[0];  // preds_s
    const float* t = (const float*)d_in[1];  // preds_t
    float* out = (float*)d_out;

    int n = in_sizes[0];
    float inv_B = (n == 4096000) ? (1.0f / 4096.0f) : (1000.0f / (float)n);

    int n_vec = n / 4;

    if ((n % 4 == 0) && (n_vec == NBLK_EX * NTHR * VPT)) {
        fused_reduce_exact<<<NBLK_EX, NTHR>>>(
            reinterpret_cast<const float4*>(s),
            reinterpret_cast<const float4*>(t),
            inv_B, out);
    } else {
        int nblk = 1024;
        fused_reduce_generic<<<nblk, NTHR>>>(s, t, n, inv_B, out, nblk);
    }
}